// round 7
// baseline (speedup 1.0000x reference)
#include <cuda_runtime.h>
#include <cuda_bf16.h>

// GraphSAGE inference, FULLY FUSED. Shapes fixed: B=4096, N0=10, N1=25, D=64, H=128.
// One block = 40 pairs = exactly 4 batch rows -> agg0 stays in registers, no h1 scratch.

#define B_     4096
#define N0_    10
#define N1_    25
#define D_     64
#define GQ     40            // pairs per block (= 4 batch rows)
#define BPB    4             // batch rows per block
#define NBLK   (B_ / BPB)    // 1024 blocks

// Weights packed (k4, j) as ulonglong2: one LDG.128 feeds two fma.rn.f32x2.
__device__ ulonglong2 g_W1q[32 * 128];   // K=128 -> 32 k4 steps
__device__ ulonglong2 g_W0q[48 * 128];   // K=192 -> 48 k4 steps

// ---- packed-fp32 helpers (f32x2 ops only reachable via PTX) ----
__device__ __forceinline__ unsigned long long pack2(float a, float b) {
    unsigned long long r;
    asm("mov.b64 %0, {%1, %2};" : "=l"(r) : "f"(a), "f"(b));
    return r;
}
__device__ __forceinline__ void unpack2(unsigned long long v, float& a, float& b) {
    asm("mov.b64 {%0, %1}, %2;" : "=f"(a), "=f"(b) : "l"(v));
}
__device__ __forceinline__ void ffma2(unsigned long long& d,
                                      unsigned long long a, unsigned long long b) {
    asm("fma.rn.f32x2 %0, %1, %2, %0;" : "+l"(d) : "l"(a), "l"(b));
}
__device__ __forceinline__ void fadd2(unsigned long long& d, unsigned long long a) {
    asm("add.rn.f32x2 %0, %0, %1;" : "+l"(d) : "l"(a));
}

// ---- merged weight pre-pack: blocks [0,32) -> W1, [32,80) -> W0 ----
__global__ void prep_w(const float* __restrict__ W1, const float* __restrict__ W0) {
    const int j = threadIdx.x;
    if (blockIdx.x < 32) {
        const int k4 = blockIdx.x;
        ulonglong2 v;
        v.x = pack2(W1[(4 * k4 + 0) * 128 + j], W1[(4 * k4 + 1) * 128 + j]);
        v.y = pack2(W1[(4 * k4 + 2) * 128 + j], W1[(4 * k4 + 3) * 128 + j]);
        g_W1q[k4 * 128 + j] = v;
    } else {
        const int k4 = blockIdx.x - 32;
        ulonglong2 v;
        v.x = pack2(W0[(4 * k4 + 0) * 128 + j], W0[(4 * k4 + 1) * 128 + j]);
        v.y = pack2(W0[(4 * k4 + 2) * 128 + j], W0[(4 * k4 + 3) * 128 + j]);
        g_W0q[k4 * 128 + j] = v;
    }
}

// ---- THE kernel: gather+mean(25)+fc1+mean(10)+fc0+sigmoid, one block = 4 b's ----
__global__ void __launch_bounds__(256, 2) sage_fused(
    const int*   __restrict__ inputs,
    const int*   __restrict__ neigh0,
    const int*   __restrict__ neigh1,
    const float* __restrict__ embed,
    const float* __restrict__ b0,
    float*       __restrict__ out)
{
    __shared__ int sn1[GQ * N1_];                    // 1000 ids
    __shared__ int sn0[GQ];
    __shared__ int sinp[BPB];
    __shared__ __align__(16) float xq[GQ][128];      // [e_n(64) | agg1(64)] per pair
    __shared__ __align__(16) float xb[BPB][192];     // [e_v(64) | agg0(128)] per b

    const int t  = threadIdx.x;
    const int p0 = blockIdx.x * GQ;                  // first pair
    const int bb = blockIdx.x * BPB;                 // first batch row

    // ---- stage indices ----
    for (int i = t; i < GQ * N1_; i += 256)
        sn1[i] = neigh1[(size_t)p0 * N1_ + i];
    if (t < GQ)   sn0[t]  = neigh0[p0 + t];
    if (t < BPB)  sinp[t] = inputs[bb + t];
    __syncthreads();

    // ---- gather: cell = (pair, c4); 640 cells over 256 threads (2-3 each) ----
    {
        const float4* eb = (const float4*)embed;
        for (int cell = t; cell < GQ * 16; cell += 256) {
            const int pr = cell >> 4;
            const int c4 = cell & 15;
            const int* nb = &sn1[pr * N1_];
            float4 s = make_float4(0.f, 0.f, 0.f, 0.f);
            #pragma unroll
            for (int i = 0; i < N1_; i++) {
                const float4 v = __ldg(eb + (size_t)nb[i] * 16 + c4);
                s.x += v.x; s.y += v.y; s.z += v.z; s.w += v.w;
            }
            const float sc = 1.f / (float)N1_;
            *(float4*)&xq[pr][64 + 4 * c4] =
                make_float4(s.x * sc, s.y * sc, s.z * sc, s.w * sc);
            *(float4*)&xq[pr][4 * c4] = __ldg(eb + (size_t)sn0[pr] * 16 + c4);
        }
        // e_v rows for fc0 (4 rows x 16 float4)
        if (t < BPB * 16) {
            const int bl = t >> 4, c4 = t & 15;
            *(float4*)&xb[bl][4 * c4] = __ldg(eb + (size_t)sinp[bl] * 16 + c4);
        }
    }
    __syncthreads();

    const int j  = t & 127;
    const int ph = t >> 7;                           // pair half: [0,20) / [20,40)

    // ---- fc1: thread (j,ph) accumulates 20 pairs; h1 never leaves registers ----
    {
        unsigned long long acc[20];
        #pragma unroll
        for (int q = 0; q < 20; q++) acc[q] = 0ull;

        #pragma unroll 2
        for (int k4 = 0; k4 < 32; k4++) {
            const ulonglong2 w = g_W1q[k4 * 128 + j];          // LDG.128 (L1-hot)
            #pragma unroll
            for (int q = 0; q < 20; q++) {
                const ulonglong2 xv =
                    *(const ulonglong2*)&xq[ph * 20 + q][4 * k4];  // LDS.128 bcast
                ffma2(acc[q], xv.x, w.x);
                ffma2(acc[q], xv.y, w.y);
            }
        }
        // ---- agg0 = mean over 10 pairs, directly from accumulators ----
        #pragma unroll
        for (int s = 0; s < 2; s++) {                // b-local = 2*ph + s
            unsigned long long ps = acc[s * 10];
            #pragma unroll
            for (int n = 1; n < N0_; n++) fadd2(ps, acc[s * 10 + n]);
            float a, b; unpack2(ps, a, b);
            xb[2 * ph + s][64 + j] = (a + b) * (1.f / (float)N0_);
        }
    }
    __syncthreads();

    // ---- fc0 + sigmoid: thread (j,ph) handles b-local {2ph, 2ph+1} ----
    {
        unsigned long long a0 = 0ull, a1 = 0ull;
        #pragma unroll 4
        for (int k4 = 0; k4 < 48; k4++) {
            const ulonglong2 w  = g_W0q[k4 * 128 + j];         // LDG.128 (L1-hot)
            const ulonglong2 x0 = *(const ulonglong2*)&xb[2 * ph + 0][4 * k4];
            const ulonglong2 x1 = *(const ulonglong2*)&xb[2 * ph + 1][4 * k4];
            ffma2(a0, x0.x, w.x); ffma2(a0, x0.y, w.y);
            ffma2(a1, x1.x, w.x); ffma2(a1, x1.y, w.y);
        }
        const float bj = __ldg(b0 + j);
        float a, b;
        unpack2(a0, a, b);
        const float h0v = a + b + bj;
        out[(size_t)(bb + 2 * ph + 0) * 128 + j] = 1.f / (1.f + __expf(-h0v));
        unpack2(a1, a, b);
        const float h1v = a + b + bj;
        out[(size_t)(bb + 2 * ph + 1) * 128 + j] = 1.f / (1.f + __expf(-h1v));
    }
}

extern "C" void kernel_launch(void* const* d_in, const int* in_sizes, int n_in,
                              void* d_out, int out_size)
{
    // Bind inputs by element count (all distinct):
    //   inputs 4096 | neigh0 40960 | neigh1 1024000 | embed 64000064
    //   W1 16384 | W0 24576 | b0 128
    const int *inputs = nullptr, *neigh0 = nullptr, *neigh1 = nullptr;
    const float *embed = nullptr, *W1 = nullptr, *W0 = nullptr, *b0 = nullptr;
    for (int i = 0; i < n_in; i++) {
        switch (in_sizes[i]) {
            case 4096:     inputs = (const int*)  d_in[i]; break;
            case 40960:    neigh0 = (const int*)  d_in[i]; break;
            case 1024000:  neigh1 = (const int*)  d_in[i]; break;
            case 64000064: embed  = (const float*)d_in[i]; break;
            case 16384:    W1     = (const float*)d_in[i]; break;
            case 24576:    W0     = (const float*)d_in[i]; break;
            case 128:      b0     = (const float*)d_in[i]; break;
        }
    }

    prep_w<<<80, 128>>>(W1, W0);
    sage_fused<<<NBLK, 256>>>(inputs, neigh0, neigh1, embed, b0, (float*)d_out);
}

// round 8
// speedup vs baseline: 1.1042x; 1.1042x over previous
#include <cuda_runtime.h>
#include <cuda_bf16.h>

// GraphSAGE inference, fully fused, occupancy-tuned.
// Shapes fixed: B=4096, N0=10, N1=25, D=64, H=128.
// One block = 20 pairs = 2 batch rows; 4 CTAs/SM for gather<->fc overlap.

#define B_     4096
#define N0_    10
#define N1_    25
#define D_     64
#define GQ     20            // pairs per block
#define BPB    2             // batch rows per block
#define NBLK   (B_ / BPB)    // 2048 blocks

// Weights packed (k4, j) as ulonglong2: one LDG.128 feeds two fma.rn.f32x2.
__device__ ulonglong2 g_W1q[32 * 128];   // K=128 -> 32 k4 steps
__device__ ulonglong2 g_W0q[48 * 128];   // K=192 -> 48 k4 steps

// ---- packed-fp32 helpers (f32x2 ops only reachable via PTX) ----
__device__ __forceinline__ unsigned long long pack2(float a, float b) {
    unsigned long long r;
    asm("mov.b64 %0, {%1, %2};" : "=l"(r) : "f"(a), "f"(b));
    return r;
}
__device__ __forceinline__ void unpack2(unsigned long long v, float& a, float& b) {
    asm("mov.b64 {%0, %1}, %2;" : "=f"(a), "=f"(b) : "l"(v));
}
__device__ __forceinline__ void ffma2(unsigned long long& d,
                                      unsigned long long a, unsigned long long b) {
    asm("fma.rn.f32x2 %0, %1, %2, %0;" : "+l"(d) : "l"(a), "l"(b));
}
__device__ __forceinline__ void fadd2(unsigned long long& d, unsigned long long a) {
    asm("add.rn.f32x2 %0, %0, %1;" : "+l"(d) : "l"(a));
}

// ---- merged weight pre-pack: blocks [0,32) -> W1, [32,80) -> W0 ----
__global__ void prep_w(const float* __restrict__ W1, const float* __restrict__ W0) {
    const int j = threadIdx.x;
    if (blockIdx.x < 32) {
        const int k4 = blockIdx.x;
        ulonglong2 v;
        v.x = pack2(W1[(4 * k4 + 0) * 128 + j], W1[(4 * k4 + 1) * 128 + j]);
        v.y = pack2(W1[(4 * k4 + 2) * 128 + j], W1[(4 * k4 + 3) * 128 + j]);
        g_W1q[k4 * 128 + j] = v;
    } else {
        const int k4 = blockIdx.x - 32;
        ulonglong2 v;
        v.x = pack2(W0[(4 * k4 + 0) * 128 + j], W0[(4 * k4 + 1) * 128 + j]);
        v.y = pack2(W0[(4 * k4 + 2) * 128 + j], W0[(4 * k4 + 3) * 128 + j]);
        g_W0q[k4 * 128 + j] = v;
    }
}

// ---- fused kernel: gather + mean(25) + fc1 + mean(10) + fc0 + sigmoid ----
__global__ void __launch_bounds__(256, 4) sage_fused(
    const int*   __restrict__ inputs,
    const int*   __restrict__ neigh0,
    const int*   __restrict__ neigh1,
    const float* __restrict__ embed,
    const float* __restrict__ b0,
    float*       __restrict__ out)
{
    __shared__ int sn1[GQ * N1_];                    // 500 ids
    __shared__ int sn0[GQ];
    __shared__ int sinp[BPB];
    __shared__ __align__(16) float xq[GQ][128];      // [e_n(64) | agg1(64)] per pair
    __shared__ __align__(16) float xb[BPB][192];     // [e_v(64) | agg0(128)] per b

    const int t  = threadIdx.x;
    const int p0 = blockIdx.x * GQ;                  // first pair
    const int bb = blockIdx.x * BPB;                 // first batch row

    // ---- stage indices ----
    for (int i = t; i < GQ * N1_; i += 256)
        sn1[i] = neigh1[(size_t)p0 * N1_ + i];
    if (t < GQ)   sn0[t]  = neigh0[p0 + t];
    if (t < BPB)  sinp[t] = inputs[bb + t];
    __syncthreads();

    // ---- gather: cell = (pair, c4); 320 cells over 256 threads ----
    {
        const float4* eb = (const float4*)embed;
        for (int cell = t; cell < GQ * 16; cell += 256) {
            const int pr = cell >> 4;
            const int c4 = cell & 15;
            const int* nb = &sn1[pr * N1_];
            float4 s = make_float4(0.f, 0.f, 0.f, 0.f);
            #pragma unroll
            for (int i = 0; i < N1_; i++) {
                const float4 v = __ldg(eb + (size_t)nb[i] * 16 + c4);
                s.x += v.x; s.y += v.y; s.z += v.z; s.w += v.w;
            }
            const float sc = 1.f / (float)N1_;
            *(float4*)&xq[pr][64 + 4 * c4] =
                make_float4(s.x * sc, s.y * sc, s.z * sc, s.w * sc);
            *(float4*)&xq[pr][4 * c4] = __ldg(eb + (size_t)sn0[pr] * 16 + c4);
        }
        // e_v rows for fc0 (2 rows x 16 float4)
        if (t < BPB * 16) {
            const int bl = t >> 4, c4 = t & 15;
            *(float4*)&xb[bl][4 * c4] = __ldg(eb + (size_t)sinp[bl] * 16 + c4);
        }
    }
    __syncthreads();

    const int j  = t & 127;
    const int ph = t >> 7;                 // pair group [0,10) / [10,20) = batch row ph

    // ---- fc1: thread (j,ph) accumulates the 10 pairs of batch row bb+ph ----
    {
        unsigned long long acc[N0_];
        #pragma unroll
        for (int q = 0; q < N0_; q++) acc[q] = 0ull;

        #pragma unroll 4
        for (int k4 = 0; k4 < 32; k4++) {
            const ulonglong2 w = g_W1q[k4 * 128 + j];          // LDG.128 (L1-hot)
            #pragma unroll
            for (int q = 0; q < N0_; q++) {
                const ulonglong2 xv =
                    *(const ulonglong2*)&xq[ph * N0_ + q][4 * k4];  // LDS.128 bcast
                ffma2(acc[q], xv.x, w.x);
                ffma2(acc[q], xv.y, w.y);
            }
        }
        // agg0 = mean over this row's 10 pairs, straight from registers
        unsigned long long ps = acc[0];
        #pragma unroll
        for (int n = 1; n < N0_; n++) fadd2(ps, acc[n]);
        float a, b; unpack2(ps, a, b);
        xb[ph][64 + j] = (a + b) * (1.f / (float)N0_);
    }
    __syncthreads();

    // ---- fc0 + sigmoid: thread (j,ph) emits out[bb+ph][j] ----
    {
        unsigned long long a0 = 0ull;
        #pragma unroll 6
        for (int k4 = 0; k4 < 48; k4++) {
            const ulonglong2 w  = g_W0q[k4 * 128 + j];         // LDG.128 (L1-hot)
            const ulonglong2 xv = *(const ulonglong2*)&xb[ph][4 * k4];
            ffma2(a0, xv.x, w.x);
            ffma2(a0, xv.y, w.y);
        }
        float a, b; unpack2(a0, a, b);
        const float hv = a + b + __ldg(b0 + j);
        out[(size_t)(bb + ph) * 128 + j] = 1.f / (1.f + __expf(-hv));
    }
}

extern "C" void kernel_launch(void* const* d_in, const int* in_sizes, int n_in,
                              void* d_out, int out_size)
{
    // Bind inputs by element count (all distinct):
    //   inputs 4096 | neigh0 40960 | neigh1 1024000 | embed 64000064
    //   W1 16384 | W0 24576 | b0 128
    const int *inputs = nullptr, *neigh0 = nullptr, *neigh1 = nullptr;
    const float *embed = nullptr, *W1 = nullptr, *W0 = nullptr, *b0 = nullptr;
    for (int i = 0; i < n_in; i++) {
        switch (in_sizes[i]) {
            case 4096:     inputs = (const int*)  d_in[i]; break;
            case 40960:    neigh0 = (const int*)  d_in[i]; break;
            case 1024000:  neigh1 = (const int*)  d_in[i]; break;
            case 64000064: embed  = (const float*)d_in[i]; break;
            case 16384:    W1     = (const float*)d_in[i]; break;
            case 24576:    W0     = (const float*)d_in[i]; break;
            case 128:      b0     = (const float*)d_in[i]; break;
        }
    }

    prep_w<<<80, 128>>>(W1, W0);
    sage_fused<<<NBLK, 256>>>(inputs, neigh0, neigh1, embed, b0, (float*)d_out);
}

// round 9
// speedup vs baseline: 1.1883x; 1.0762x over previous
#include <cuda_runtime.h>
#include <cuda_bf16.h>

// GraphSAGE inference — warp-specialized producer/consumer pipeline.
// Shapes fixed: B=4096, N0=10, N1=25, D=64, H=128.
// Tile = 2 batch rows = 20 pairs. 2048 tiles, 296 persistent-ish CTAs (2/SM).
// Warps 0-3: gather (ids -> embed rows -> mean -> xq). Warps 4-7: fc1+fc0.

#define B_     4096
#define N0_    10
#define N1_    25
#define D_     64
#define TGQ    20           // pairs per tile
#define TBPB   2            // batch rows per tile
#define TILES  (B_ / TBPB)  // 2048
#define GRID   296          // = 2 * 148 SMs

// Weights packed for jt=2: per (k4, j2) a 32B record = {col j=2*j2, col j=2*j2+1},
// each col entry an ulonglong2 of 4 packed-f32x2 K values -> LDG.128 x2 feeds 8 ffma2.
__device__ ulonglong2 g_W1d[32 * 64 * 2];   // K=128: 32 k4 steps
__device__ ulonglong2 g_W0d[48 * 64 * 2];   // K=192: 48 k4 steps

// ---- packed-fp32 helpers (f32x2 only reachable via PTX) ----
__device__ __forceinline__ unsigned long long pack2(float a, float b) {
    unsigned long long r;
    asm("mov.b64 %0, {%1, %2};" : "=l"(r) : "f"(a), "f"(b));
    return r;
}
__device__ __forceinline__ void unpack2(unsigned long long v, float& a, float& b) {
    asm("mov.b64 {%0, %1}, %2;" : "=f"(a), "=f"(b) : "l"(v));
}
__device__ __forceinline__ void ffma2(unsigned long long& d,
                                      unsigned long long a, unsigned long long b) {
    asm("fma.rn.f32x2 %0, %1, %2, %0;" : "+l"(d) : "l"(a), "l"(b));
}
__device__ __forceinline__ void fadd2(unsigned long long& d, unsigned long long a) {
    asm("add.rn.f32x2 %0, %0, %1;" : "+l"(d) : "l"(a));
}

// ---- weight pre-pack: blocks [0,32) -> W1, [32,80) -> W0 ----
__global__ void prep_w(const float* __restrict__ W1, const float* __restrict__ W0) {
    const int j  = threadIdx.x;            // 0..127 output column
    const int j2 = j >> 1, jt = j & 1;
    if (blockIdx.x < 32) {
        const int k4 = blockIdx.x;
        ulonglong2 v;
        v.x = pack2(W1[(4 * k4 + 0) * 128 + j], W1[(4 * k4 + 1) * 128 + j]);
        v.y = pack2(W1[(4 * k4 + 2) * 128 + j], W1[(4 * k4 + 3) * 128 + j]);
        g_W1d[(k4 * 64 + j2) * 2 + jt] = v;
    } else {
        const int k4 = blockIdx.x - 32;
        ulonglong2 v;
        v.x = pack2(W0[(4 * k4 + 0) * 128 + j], W0[(4 * k4 + 1) * 128 + j]);
        v.y = pack2(W0[(4 * k4 + 2) * 128 + j], W0[(4 * k4 + 3) * 128 + j]);
        g_W0d[(k4 * 64 + j2) * 2 + jt] = v;
    }
}

// ---- the pipelined kernel ----
__global__ void __launch_bounds__(256, 2) sage_pipe(
    const int*   __restrict__ inputs,
    const int*   __restrict__ neigh0,
    const int*   __restrict__ neigh1,
    const float* __restrict__ embed,
    const float* __restrict__ b0,
    float*       __restrict__ out)
{
    __shared__ int sn1[2][TGQ * N1_];                    // 2 x 500 ids
    __shared__ __align__(16) float xq[2][TGQ][128];      // [e_n(64)|agg1(64)]
    __shared__ __align__(16) float xb[2][TBPB][192];     // [e_v(64)|agg0(128)]

    const int t = threadIdx.x;
    const int w = t >> 5;
    // number of tiles this CTA owns: tiles bid, bid+GRID, ...
    const int nt = (TILES - 1 - (int)blockIdx.x) / GRID + 1;

    for (int it = 0; it <= nt; it++) {
        if (w < 4) {
            // ================= GATHER warps (producer) =================
            if (it < nt) {
                const int tt = blockIdx.x + it * GRID;   // tile to gather
                const int gb = it & 1;                   // buffer to fill
                const int p0 = tt * TGQ;
                const int bb = tt * TBPB;
                const int gt = t;                        // 0..127

                // stage level-1 neighbor ids
                for (int i = gt; i < TGQ * N1_; i += 128)
                    sn1[gb][i] = neigh1[(size_t)p0 * N1_ + i];
                asm volatile("bar.sync 1, 128;" ::: "memory");

                const float4* eb = (const float4*)embed;
                // e_v rows for fc0 (2 rows x 16 float4)
                if (gt < TBPB * 16) {
                    const int row = gt >> 4, c4 = gt & 15;
                    const int node = __ldg(inputs + bb + row);
                    *(float4*)&xb[gb][row][4 * c4] =
                        __ldg(eb + (size_t)node * 16 + c4);
                }
                // cells: (pair, c4) = 320 cells over 128 threads (2-3 each)
                for (int cell = gt; cell < TGQ * 16; cell += 128) {
                    const int pr = cell >> 4;
                    const int c4 = cell & 15;
                    const int* nb = &sn1[gb][pr * N1_];
                    float4 s = make_float4(0.f, 0.f, 0.f, 0.f);
                    #pragma unroll
                    for (int i = 0; i < N1_; i++) {
                        const float4 v = __ldg(eb + (size_t)nb[i] * 16 + c4);
                        s.x += v.x; s.y += v.y; s.z += v.z; s.w += v.w;
                    }
                    const int n0 = __ldg(neigh0 + p0 + pr);
                    *(float4*)&xq[gb][pr][4 * c4] =
                        __ldg(eb + (size_t)n0 * 16 + c4);
                    const float sc = 1.f / (float)N1_;
                    *(float4*)&xq[gb][pr][64 + 4 * c4] =
                        make_float4(s.x * sc, s.y * sc, s.z * sc, s.w * sc);
                }
            }
        } else {
            // ================= FC warps (consumer) =================
            if (it > 0) {
                const int tt = blockIdx.x + (it - 1) * GRID;  // tile to compute
                const int fb = (it - 1) & 1;                  // buffer to read
                const int bb = tt * TBPB;
                const int ft  = t - 128;                      // 0..127
                const int j2  = ft & 63;                      // j = 2*j2, 2*j2+1
                const int row = ft >> 6;                      // 0..1

                // ---- fc1: jt=2 x qt=10 register tile ----
                unsigned long long acc0[N0_], acc1[N0_];
                #pragma unroll
                for (int q = 0; q < N0_; q++) { acc0[q] = 0ull; acc1[q] = 0ull; }

                #pragma unroll 4
                for (int k4 = 0; k4 < 32; k4++) {
                    const ulonglong2 wa = g_W1d[(k4 * 64 + j2) * 2 + 0];  // LDG.128
                    const ulonglong2 wb = g_W1d[(k4 * 64 + j2) * 2 + 1];  // LDG.128
                    #pragma unroll
                    for (int q = 0; q < N0_; q++) {
                        const ulonglong2 xv =
                            *(const ulonglong2*)&xq[fb][row * N0_ + q][4 * k4];
                        ffma2(acc0[q], xv.x, wa.x); ffma2(acc0[q], xv.y, wa.y);
                        ffma2(acc1[q], xv.x, wb.x); ffma2(acc1[q], xv.y, wb.y);
                    }
                }
                // agg0 = mean over 10 pairs, straight from registers
                {
                    unsigned long long p0s = acc0[0], p1s = acc1[0];
                    #pragma unroll
                    for (int n = 1; n < N0_; n++) { fadd2(p0s, acc0[n]); fadd2(p1s, acc1[n]); }
                    float a, b;
                    unpack2(p0s, a, b);
                    xb[fb][row][64 + 2 * j2 + 0] = (a + b) * (1.f / (float)N0_);
                    unpack2(p1s, a, b);
                    xb[fb][row][64 + 2 * j2 + 1] = (a + b) * (1.f / (float)N0_);
                }
                asm volatile("bar.sync 2, 128;" ::: "memory");

                // ---- fc0 + sigmoid ----
                unsigned long long a0 = 0ull, a1 = 0ull;
                #pragma unroll 6
                for (int k4 = 0; k4 < 48; k4++) {
                    const ulonglong2 wa = g_W0d[(k4 * 64 + j2) * 2 + 0];
                    const ulonglong2 wb = g_W0d[(k4 * 64 + j2) * 2 + 1];
                    const ulonglong2 xv = *(const ulonglong2*)&xb[fb][row][4 * k4];
                    ffma2(a0, xv.x, wa.x); ffma2(a0, xv.y, wa.y);
                    ffma2(a1, xv.x, wb.x); ffma2(a1, xv.y, wb.y);
                }
                float a, b;
                unpack2(a0, a, b);
                const float h0 = a + b + __ldg(b0 + 2 * j2 + 0);
                unpack2(a1, a, b);
                const float h1 = a + b + __ldg(b0 + 2 * j2 + 1);
                float2 r;
                r.x = 1.f / (1.f + __expf(-h0));
                r.y = 1.f / (1.f + __expf(-h1));
                ((float2*)out)[(size_t)(bb + row) * 64 + j2] = r;
            }
        }
        __syncthreads();   // tile boundary: swap buffers
    }
}

extern "C" void kernel_launch(void* const* d_in, const int* in_sizes, int n_in,
                              void* d_out, int out_size)
{
    // Bind inputs by element count (all distinct):
    //   inputs 4096 | neigh0 40960 | neigh1 1024000 | embed 64000064
    //   W1 16384 | W0 24576 | b0 128
    const int *inputs = nullptr, *neigh0 = nullptr, *neigh1 = nullptr;
    const float *embed = nullptr, *W1 = nullptr, *W0 = nullptr, *b0 = nullptr;
    for (int i = 0; i < n_in; i++) {
        switch (in_sizes[i]) {
            case 4096:     inputs = (const int*)  d_in[i]; break;
            case 40960:    neigh0 = (const int*)  d_in[i]; break;
            case 1024000:  neigh1 = (const int*)  d_in[i]; break;
            case 64000064: embed  = (const float*)d_in[i]; break;
            case 16384:    W1     = (const float*)d_in[i]; break;
            case 24576:    W0     = (const float*)d_in[i]; break;
            case 128:      b0     = (const float*)d_in[i]; break;
        }
    }

    prep_w<<<80, 128>>>(W1, W0);
    sage_pipe<<<GRID, 256>>>(inputs, neigh0, neigh1, embed, b0, (float*)d_out);
}

// round 10
// speedup vs baseline: 1.8034x; 1.5176x over previous
#include <cuda_runtime.h>
#include <cuda_bf16.h>

// GraphSAGE inference — algebraically reduced.
// KEY: fc1 is linear and agg0 is a mean =>
//   agg0[b] = (mean_n [e_n(b,n) | mean_nn e_nn(b,n,:)]) @ W1  -- ONE gemv per row.
// So: per batch row, sum 250 neigh1 embeds and 10 neigh0 embeds, then 2 tiny gemvs.
// Shapes fixed: B=4096, N0=10, N1=25, D=64, H=128.

#define B_     4096
#define N0_    10
#define N1_    25
#define D_     64
#define GB     8            // batch rows per block
#define NBLK   (B_ / GB)    // 512

// Weights packed (k4, j) as ulonglong2 (jt=1: lane stride 16B -> 4 wf/LDG.128).
__device__ ulonglong2 g_W1q[32 * 128];   // K=128
__device__ ulonglong2 g_W0q[48 * 128];   // K=192

// ---- packed-fp32 helpers (f32x2 only via PTX) ----
__device__ __forceinline__ unsigned long long pack2(float a, float b) {
    unsigned long long r;
    asm("mov.b64 %0, {%1, %2};" : "=l"(r) : "f"(a), "f"(b));
    return r;
}
__device__ __forceinline__ void unpack2(unsigned long long v, float& a, float& b) {
    asm("mov.b64 {%0, %1}, %2;" : "=f"(a), "=f"(b) : "l"(v));
}
__device__ __forceinline__ void ffma2(unsigned long long& d,
                                      unsigned long long a, unsigned long long b) {
    asm("fma.rn.f32x2 %0, %1, %2, %0;" : "+l"(d) : "l"(a), "l"(b));
}

__global__ void prep_w(const float* __restrict__ W1, const float* __restrict__ W0) {
    const int j = threadIdx.x;
    if (blockIdx.x < 32) {
        const int k4 = blockIdx.x;
        ulonglong2 v;
        v.x = pack2(W1[(4 * k4 + 0) * 128 + j], W1[(4 * k4 + 1) * 128 + j]);
        v.y = pack2(W1[(4 * k4 + 2) * 128 + j], W1[(4 * k4 + 3) * 128 + j]);
        g_W1q[k4 * 128 + j] = v;
    } else {
        const int k4 = blockIdx.x - 32;
        ulonglong2 v;
        v.x = pack2(W0[(4 * k4 + 0) * 128 + j], W0[(4 * k4 + 1) * 128 + j]);
        v.y = pack2(W0[(4 * k4 + 2) * 128 + j], W0[(4 * k4 + 3) * 128 + j]);
        g_W0q[k4 * 128 + j] = v;
    }
}

__global__ void __launch_bounds__(256, 4) sage_v2(
    const int*   __restrict__ inputs,
    const int*   __restrict__ neigh0,
    const int*   __restrict__ neigh1,
    const float* __restrict__ embed,
    const float* __restrict__ b0,
    float*       __restrict__ out)
{
    __shared__ int sn1[2][N0_ * N1_];                 // 250 ids x 2 rows per pass
    __shared__ __align__(16) float part[16][4][64];   // [worker][n1a,n0a,n1b,n0b][c]
    __shared__ __align__(16) float xbar[GB][128];     // [sum(e_n)/10 | sum(e_nn)/250]
    __shared__ __align__(16) float xb[GB][192];       // [e_v | agg0]

    const int t  = threadIdx.x;
    const int bb = blockIdx.x * GB;
    const float4* eb = (const float4*)embed;

    // e_v rows (8 x 16 float4), once
    if (t < GB * 16) {
        const int row = t >> 4, c4 = t & 15;
        const int node = __ldg(inputs + bb + row);
        *(float4*)&xb[row][4 * c4] = __ldg(eb + (size_t)node * 16 + c4);
    }

    const int c4 = t & 15;          // column slot (16 x float4 = 256B row)
    const int w  = t >> 4;          // worker 0..15

    // ---- gather: 4 passes of 2 rows; worker w sums ids w, w+16, ... ----
    #pragma unroll 1
    for (int pass = 0; pass < GB / 2; pass++) {
        const int ra = 2 * pass, rb = 2 * pass + 1;
        if (t < N0_ * N1_) {
            sn1[0][t] = neigh1[(size_t)(bb + ra) * (N0_ * N1_) + t];
            sn1[1][t] = neigh1[(size_t)(bb + rb) * (N0_ * N1_) + t];
        }
        __syncthreads();

        float4 s1a = make_float4(0.f, 0.f, 0.f, 0.f);
        float4 s1b = make_float4(0.f, 0.f, 0.f, 0.f);
        #pragma unroll 5
        for (int i = w; i < N0_ * N1_; i += 16) {
            const float4 va = __ldg(eb + (size_t)sn1[0][i] * 16 + c4);
            const float4 vb = __ldg(eb + (size_t)sn1[1][i] * 16 + c4);
            s1a.x += va.x; s1a.y += va.y; s1a.z += va.z; s1a.w += va.w;
            s1b.x += vb.x; s1b.y += vb.y; s1b.z += vb.z; s1b.w += vb.w;
        }
        float4 s0a = make_float4(0.f, 0.f, 0.f, 0.f);
        float4 s0b = make_float4(0.f, 0.f, 0.f, 0.f);
        if (w < N0_) {
            s0a = __ldg(eb + (size_t)__ldg(neigh0 + (bb + ra) * N0_ + w) * 16 + c4);
            s0b = __ldg(eb + (size_t)__ldg(neigh0 + (bb + rb) * N0_ + w) * 16 + c4);
        }
        *(float4*)&part[w][0][4 * c4] = s1a;
        *(float4*)&part[w][1][4 * c4] = s0a;
        *(float4*)&part[w][2][4 * c4] = s1b;
        *(float4*)&part[w][3][4 * c4] = s0b;
        __syncthreads();

        // reduce 16 workers: thread (v = t>>6, c = t&63)
        {
            const int v = t >> 6, c = t & 63;
            float s = 0.f;
            #pragma unroll
            for (int ww = 0; ww < 16; ww++) s += part[ww][v][c];
            if (v == 0)      xbar[ra][64 + c] = s * (1.f / 250.f);
            else if (v == 1) xbar[ra][c]      = s * (1.f / 10.f);
            else if (v == 2) xbar[rb][64 + c] = s * (1.f / 250.f);
            else             xbar[rb][c]      = s * (1.f / 10.f);
        }
        __syncthreads();
    }

    const int j = t & 127;
    const int h = t >> 7;           // rows h*4 .. h*4+3

    // ---- fc1: agg0[r] = xbar[r] @ W1 (4 rows per thread) ----
    {
        unsigned long long acc[4] = {0ull, 0ull, 0ull, 0ull};
        #pragma unroll 4
        for (int k4 = 0; k4 < 32; k4++) {
            const ulonglong2 wv = g_W1q[k4 * 128 + j];
            #pragma unroll
            for (int r = 0; r < 4; r++) {
                const ulonglong2 xv = *(const ulonglong2*)&xbar[h * 4 + r][4 * k4];
                ffma2(acc[r], xv.x, wv.x);
                ffma2(acc[r], xv.y, wv.y);
            }
        }
        #pragma unroll
        for (int r = 0; r < 4; r++) {
            float a, b; unpack2(acc[r], a, b);
            xb[h * 4 + r][64 + j] = a + b;
        }
    }
    __syncthreads();

    // ---- fc0 + sigmoid ----
    {
        unsigned long long acc[4] = {0ull, 0ull, 0ull, 0ull};
        #pragma unroll 4
        for (int k4 = 0; k4 < 48; k4++) {
            const ulonglong2 wv = g_W0q[k4 * 128 + j];
            #pragma unroll
            for (int r = 0; r < 4; r++) {
                const ulonglong2 xv = *(const ulonglong2*)&xb[h * 4 + r][4 * k4];
                ffma2(acc[r], xv.x, wv.x);
                ffma2(acc[r], xv.y, wv.y);
            }
        }
        const float bj = __ldg(b0 + j);
        #pragma unroll
        for (int r = 0; r < 4; r++) {
            float a, b; unpack2(acc[r], a, b);
            const float hv = a + b + bj;
            out[(size_t)(bb + h * 4 + r) * 128 + j] = 1.f / (1.f + __expf(-hv));
        }
    }
}

extern "C" void kernel_launch(void* const* d_in, const int* in_sizes, int n_in,
                              void* d_out, int out_size)
{
    // Bind inputs by element count (all distinct):
    //   inputs 4096 | neigh0 40960 | neigh1 1024000 | embed 64000064
    //   W1 16384 | W0 24576 | b0 128
    const int *inputs = nullptr, *neigh0 = nullptr, *neigh1 = nullptr;
    const float *embed = nullptr, *W1 = nullptr, *W0 = nullptr, *b0 = nullptr;
    for (int i = 0; i < n_in; i++) {
        switch (in_sizes[i]) {
            case 4096:     inputs = (const int*)  d_in[i]; break;
            case 40960:    neigh0 = (const int*)  d_in[i]; break;
            case 1024000:  neigh1 = (const int*)  d_in[i]; break;
            case 64000064: embed  = (const float*)d_in[i]; break;
            case 16384:    W1     = (const float*)d_in[i]; break;
            case 24576:    W0     = (const float*)d_in[i]; break;
            case 128:      b0     = (const float*)d_in[i]; break;
        }
    }

    prep_w<<<80, 128>>>(W1, W0);
    sage_v2<<<NBLK, 256>>>(inputs, neigh0, neigh1, embed, b0, (float*)d_out);
}

// round 11
// speedup vs baseline: 1.8779x; 1.0413x over previous
#include <cuda_runtime.h>
#include <cuda_bf16.h>

// GraphSAGE inference — algebraic reduction + warp-autonomous gather.
//   agg0[b] = (mean_n [e_n | mean_nn e_nn]) @ W1   (fc1 linear => commutes with mean)
// One warp = one batch row: stage ids, gather-sum 250+10 embed rows, shfl-reduce.
// No block barriers until the tiny fc phase. Shapes: B=4096,N0=10,N1=25,D=64,H=128.

#define B_     4096
#define N0_    10
#define N1_    25
#define D_     64
#define GB     8            // batch rows per block = warps per block
#define NBLK   (B_ / GB)    // 512 blocks (single wave at 4 CTAs/SM)
#define SNW    272          // ints per warp id buffer (250 n1 + 10 n0, padded)

// Weights packed (k4, j) as ulonglong2 of packed-f32x2 K values.
__device__ ulonglong2 g_W1q[32 * 128];   // K=128
__device__ ulonglong2 g_W0q[48 * 128];   // K=192

// ---- packed-fp32 helpers (f32x2 only via PTX) ----
__device__ __forceinline__ unsigned long long pack2(float a, float b) {
    unsigned long long r;
    asm("mov.b64 %0, {%1, %2};" : "=l"(r) : "f"(a), "f"(b));
    return r;
}
__device__ __forceinline__ void unpack2(unsigned long long v, float& a, float& b) {
    asm("mov.b64 {%0, %1}, %2;" : "=f"(a), "=f"(b) : "l"(v));
}
__device__ __forceinline__ void ffma2(unsigned long long& d,
                                      unsigned long long a, unsigned long long b) {
    asm("fma.rn.f32x2 %0, %1, %2, %0;" : "+l"(d) : "l"(a), "l"(b));
}

__global__ void prep_w(const float* __restrict__ W1, const float* __restrict__ W0) {
    const int j = threadIdx.x;
    if (blockIdx.x < 32) {
        const int k4 = blockIdx.x;
        ulonglong2 v;
        v.x = pack2(W1[(4 * k4 + 0) * 128 + j], W1[(4 * k4 + 1) * 128 + j]);
        v.y = pack2(W1[(4 * k4 + 2) * 128 + j], W1[(4 * k4 + 3) * 128 + j]);
        g_W1q[k4 * 128 + j] = v;
    } else {
        const int k4 = blockIdx.x - 32;
        ulonglong2 v;
        v.x = pack2(W0[(4 * k4 + 0) * 128 + j], W0[(4 * k4 + 1) * 128 + j]);
        v.y = pack2(W0[(4 * k4 + 2) * 128 + j], W0[(4 * k4 + 3) * 128 + j]);
        g_W0q[k4 * 128 + j] = v;
    }
}

__global__ void __launch_bounds__(256, 4) sage_v3(
    const int*   __restrict__ inputs,
    const int*   __restrict__ neigh0,
    const int*   __restrict__ neigh1,
    const float* __restrict__ embed,
    const float* __restrict__ b0,
    float*       __restrict__ out)
{
    __shared__ int snbuf[GB * SNW];                  // per-warp id staging
    __shared__ __align__(16) float xbar[GB][128];    // [sum(e_n)/10 | sum(e_nn)/250]
    __shared__ __align__(16) float xb[GB][192];      // [e_v | agg0]

    const int t    = threadIdx.x;
    const int w    = t >> 5;                         // warp = local batch row
    const int lane = t & 31;
    const int c4   = lane & 15;                      // float4 column slot
    const int hh   = lane >> 4;                      // even/odd id half
    const int row  = blockIdx.x * GB + w;            // global batch row
    const float4* eb = (const float4*)embed;
    int* sn = &snbuf[w * SNW];

    // ---- stage this warp's ids (warp-private, no block sync) ----
    for (int i = lane; i < N0_ * N1_; i += 32)
        sn[i] = __ldg(neigh1 + (size_t)row * (N0_ * N1_) + i);
    if (lane < N0_)
        sn[250 + lane] = __ldg(neigh0 + row * N0_ + lane);
    __syncwarp();

    // ---- gather-sum: half hh sums ids hh, hh+2, ... (125 of 250) ----
    float4 a1 = make_float4(0.f, 0.f, 0.f, 0.f);
    {
        const int* sni = sn + hh;
        #pragma unroll 1
        for (int it = 0; it < 25; it++) {            // 25 batches x 5 loads
            const int base = it * 10;
            const float4 v0 = __ldg(eb + (size_t)sni[base + 0] * 16 + c4);
            const float4 v1 = __ldg(eb + (size_t)sni[base + 2] * 16 + c4);
            const float4 v2 = __ldg(eb + (size_t)sni[base + 4] * 16 + c4);
            const float4 v3 = __ldg(eb + (size_t)sni[base + 6] * 16 + c4);
            const float4 v4 = __ldg(eb + (size_t)sni[base + 8] * 16 + c4);
            a1.x += v0.x + v1.x + v2.x + v3.x + v4.x;
            a1.y += v0.y + v1.y + v2.y + v3.y + v4.y;
            a1.z += v0.z + v1.z + v2.z + v3.z + v4.z;
            a1.w += v0.w + v1.w + v2.w + v3.w + v4.w;
        }
    }
    // neigh0: 5 ids per half
    float4 a0;
    {
        const int* sn0 = sn + 250 + hh;
        const float4 u0 = __ldg(eb + (size_t)sn0[0] * 16 + c4);
        const float4 u1 = __ldg(eb + (size_t)sn0[2] * 16 + c4);
        const float4 u2 = __ldg(eb + (size_t)sn0[4] * 16 + c4);
        const float4 u3 = __ldg(eb + (size_t)sn0[6] * 16 + c4);
        const float4 u4 = __ldg(eb + (size_t)sn0[8] * 16 + c4);
        a0 = make_float4(u0.x + u1.x + u2.x + u3.x + u4.x,
                         u0.y + u1.y + u2.y + u3.y + u4.y,
                         u0.z + u1.z + u2.z + u3.z + u4.z,
                         u0.w + u1.w + u2.w + u3.w + u4.w);
    }
    // e_v row (upper half loads it while lower half reduces)
    float4 ev = make_float4(0.f, 0.f, 0.f, 0.f);
    if (hh == 1)
        ev = __ldg(eb + (size_t)__ldg(inputs + row) * 16 + c4);

    // ---- combine halves via shfl.xor 16 (warp-local) ----
    a1.x += __shfl_xor_sync(0xffffffffu, a1.x, 16);
    a1.y += __shfl_xor_sync(0xffffffffu, a1.y, 16);
    a1.z += __shfl_xor_sync(0xffffffffu, a1.z, 16);
    a1.w += __shfl_xor_sync(0xffffffffu, a1.w, 16);
    a0.x += __shfl_xor_sync(0xffffffffu, a0.x, 16);
    a0.y += __shfl_xor_sync(0xffffffffu, a0.y, 16);
    a0.z += __shfl_xor_sync(0xffffffffu, a0.z, 16);
    a0.w += __shfl_xor_sync(0xffffffffu, a0.w, 16);

    if (hh == 0) {
        const float s1 = 1.f / 250.f, s0 = 1.f / 10.f;
        *(float4*)&xbar[w][64 + 4 * c4] =
            make_float4(a1.x * s1, a1.y * s1, a1.z * s1, a1.w * s1);
        *(float4*)&xbar[w][4 * c4] =
            make_float4(a0.x * s0, a0.y * s0, a0.z * s0, a0.w * s0);
    } else {
        *(float4*)&xb[w][4 * c4] = ev;
    }
    __syncthreads();                                 // the ONLY block barrier pre-fc

    const int j = t & 127;
    const int h2 = t >> 7;                           // rows h2*4 .. h2*4+3

    // ---- fc1: agg0[r] = xbar[r] @ W1 (4 rows per thread) ----
    {
        unsigned long long acc[4] = {0ull, 0ull, 0ull, 0ull};
        #pragma unroll 4
        for (int k4 = 0; k4 < 32; k4++) {
            const ulonglong2 wv = g_W1q[k4 * 128 + j];
            #pragma unroll
            for (int r = 0; r < 4; r++) {
                const ulonglong2 xv = *(const ulonglong2*)&xbar[h2 * 4 + r][4 * k4];
                ffma2(acc[r], xv.x, wv.x);
                ffma2(acc[r], xv.y, wv.y);
            }
        }
        #pragma unroll
        for (int r = 0; r < 4; r++) {
            float a, b; unpack2(acc[r], a, b);
            xb[h2 * 4 + r][64 + j] = a + b;
        }
    }
    __syncthreads();

    // ---- fc0 + sigmoid ----
    {
        unsigned long long acc[4] = {0ull, 0ull, 0ull, 0ull};
        #pragma unroll 4
        for (int k4 = 0; k4 < 48; k4++) {
            const ulonglong2 wv = g_W0q[k4 * 128 + j];
            #pragma unroll
            for (int r = 0; r < 4; r++) {
                const ulonglong2 xv = *(const ulonglong2*)&xb[h2 * 4 + r][4 * k4];
                ffma2(acc[r], xv.x, wv.x);
                ffma2(acc[r], xv.y, wv.y);
            }
        }
        const float bj = __ldg(b0 + j);
        const int bb = blockIdx.x * GB;
        #pragma unroll
        for (int r = 0; r < 4; r++) {
            float a, b; unpack2(acc[r], a, b);
            const float hv = a + b + bj;
            out[(size_t)(bb + h2 * 4 + r) * 128 + j] = 1.f / (1.f + __expf(-hv));
        }
    }
}

extern "C" void kernel_launch(void* const* d_in, const int* in_sizes, int n_in,
                              void* d_out, int out_size)
{
    // Bind inputs by element count (all distinct):
    //   inputs 4096 | neigh0 40960 | neigh1 1024000 | embed 64000064
    //   W1 16384 | W0 24576 | b0 128
    const int *inputs = nullptr, *neigh0 = nullptr, *neigh1 = nullptr;
    const float *embed = nullptr, *W1 = nullptr, *W0 = nullptr, *b0 = nullptr;
    for (int i = 0; i < n_in; i++) {
        switch (in_sizes[i]) {
            case 4096:     inputs = (const int*)  d_in[i]; break;
            case 40960:    neigh0 = (const int*)  d_in[i]; break;
            case 1024000:  neigh1 = (const int*)  d_in[i]; break;
            case 64000064: embed  = (const float*)d_in[i]; break;
            case 16384:    W1     = (const float*)d_in[i]; break;
            case 24576:    W0     = (const float*)d_in[i]; break;
            case 128:      b0     = (const float*)d_in[i]; break;
        }
    }

    prep_w<<<80, 128>>>(W1, W0);
    sage_v3<<<NBLK, 256>>>(inputs, neigh0, neigh1, embed, b0, (float*)d_out);
}